// round 16
// baseline (speedup 1.0000x reference)
#include <cuda_runtime.h>
#include <math.h>
#include <stdint.h>

#define NN 512
#define DD 512
#define LN_EPS 1e-5f

typedef unsigned long long ull;

// ---------------- f32x2 packed helpers ----------------
__device__ __forceinline__ ull pk(float lo, float hi) {
    ull r; asm("mov.b64 %0, {%1, %2};" : "=l"(r) : "f"(lo), "f"(hi)); return r;
}
__device__ __forceinline__ ull pkdup(float v) {
    ull r; asm("mov.b64 %0, {%1, %1};" : "=l"(r) : "f"(v)); return r;
}
__device__ __forceinline__ void upk(ull v, float& lo, float& hi) {
    asm("mov.b64 {%0, %1}, %2;" : "=f"(lo), "=f"(hi) : "l"(v));
}
__device__ __forceinline__ ull fma2(ull a, ull b, ull c) {
    ull r; asm("fma.rn.f32x2 %0, %1, %2, %3;" : "=l"(r) : "l"(a), "l"(b), "l"(c)); return r;
}
__device__ __forceinline__ ull add2(ull a, ull b) {
    ull r; asm("add.rn.f32x2 %0, %1, %2;" : "=l"(r) : "l"(a), "l"(b)); return r;
}
__device__ __forceinline__ ull mul2(ull a, ull b) {
    ull r; asm("mul.rn.f32x2 %0, %1, %2;" : "=l"(r) : "l"(a), "l"(b)); return r;
}
__device__ __forceinline__ float tanh_approx(float x) {
    float r; asm("tanh.approx.f32 %0, %1;" : "=f"(r) : "f"(x)); return r;
}
__device__ __forceinline__ void mma_tf32(float4& d,
    uint32_t a0, uint32_t a1, uint32_t a2, uint32_t a3,
    uint32_t b0, uint32_t b1)
{
    asm("mma.sync.aligned.m16n8k8.row.col.f32.tf32.tf32.f32 "
        "{%0,%1,%2,%3}, {%4,%5,%6,%7}, {%8,%9}, {%0,%1,%2,%3};"
        : "+f"(d.x), "+f"(d.y), "+f"(d.z), "+f"(d.w)
        : "r"(a0), "r"(a1), "r"(a2), "r"(a3), "r"(b0), "r"(b1));
}
__device__ __forceinline__ uint32_t smem_u32(const void* p) {
    uint32_t a;
    asm("{ .reg .u64 tmp; cvta.to.shared.u64 tmp, %1; cvt.u32.u64 %0, tmp; }"
        : "=r"(a) : "l"(p));
    return a;
}
__device__ __forceinline__ void cp16(uint32_t dst, const void* src) {
    asm volatile("cp.async.cg.shared.global [%0], [%1], 16;"
                 :: "r"(dst), "l"(src) : "memory");
}
#define CP_COMMIT() asm volatile("cp.async.commit_group;" ::: "memory")
#define CP_WAIT1()  asm volatile("cp.async.wait_group 1;" ::: "memory")

// Scratch (all L2-resident):
__device__ float g_LR[2 * NN * DD];   // left rows, then right rows (2 MB)
__device__ float g_C[NN * NN];        // cross dot L_i . R_j (upper tiles)
__device__ float g_S[2 * NN];         // row sums (L then R)
__device__ float g_Q[2 * NN];         // row sumsq
__device__ float g_A[2 * NN];         // dot(w*gamma, row)
__device__ float g_K[2];              // K1 = sum w*gamma, K2 = sum w*beta

extern __shared__ float smem_dyn[];

// ---------------------------------------------------------------------------
// Tensor-core GEMM (R11-measured, 11.3us): 64x64 tile, 256 threads (8 warps,
// warp tile 16x32), BK=64, 8 iterations, 3 full buffers, cp.async 2 ahead.
// ---------------------------------------------------------------------------
#define GA_STRIDE 68
#define GB_STRIDE 72
#define GA_BUF (64 * GA_STRIDE)
#define GB_BUF (64 * GB_STRIDE)
#define GEMM_SMEM (3 * (GA_BUF + GB_BUF) * 4)   // 107,520 B

__global__ __launch_bounds__(256) void gemm_tc(
    const float* __restrict__ E, const float* __restrict__ W1,
    const float* __restrict__ b1)
{
    float (*As)[64][GA_STRIDE] = (float(*)[64][GA_STRIDE])smem_dyn;
    float (*Bs)[64][GB_STRIDE] = (float(*)[64][GB_STRIDE])(smem_dyn + 3 * GA_BUF);

    const int z = blockIdx.z;
    const float* W = W1 + z * DD * DD;
    float* out = g_LR + z * NN * DD;

    const int m0 = blockIdx.y * 64;
    const int n0 = blockIdx.x * 64;
    const int t = threadIdx.x;
    const int lane = t & 31;
    const int w = t >> 5;
    const int g = lane >> 2, tig = lane & 3;
    const int mrow0 = (w >> 1) * 16;
    const int ncol0 = (w & 1) * 32;

    const int sr = t >> 4;
    const int sc = (t & 15) << 2;

    uint32_t a0addr[4], b0addr[4];
#pragma unroll
    for (int r = 0; r < 4; r++) {
        a0addr[r] = smem_u32(&As[0][sr + 16 * r][sc]);
        b0addr[r] = smem_u32(&Bs[0][sr + 16 * r][sc]);
    }

#define GEMM_ISSUE(p, k0)                                                     \
    {                                                                         \
        uint32_t ao = (uint32_t)(p) * (GA_BUF * 4);                           \
        uint32_t bo = (uint32_t)(p) * (GB_BUF * 4);                           \
        _Pragma("unroll")                                                     \
        for (int r = 0; r < 4; r++) {                                         \
            cp16(a0addr[r] + ao, &E[(m0 + sr + 16 * r) * DD + (k0) + sc]);    \
            cp16(b0addr[r] + bo, &W[((k0) + sr + 16 * r) * DD + n0 + sc]);    \
        }                                                                     \
    }

    GEMM_ISSUE(0, 0);  CP_COMMIT();
    GEMM_ISSUE(1, 64); CP_COMMIT();

    float4 acc[4];
#pragma unroll
    for (int nt = 0; nt < 4; nt++) acc[nt] = make_float4(0.f, 0.f, 0.f, 0.f);

    for (int it = 0; it < 8; it++) {
        CP_WAIT1();
        __syncthreads();
        if (it < 6) {
            const int p = (it + 2) % 3;
            GEMM_ISSUE(p, (it + 2) * 64);
        }
        CP_COMMIT();

        const int p = it % 3;
#pragma unroll
        for (int kk = 0; kk < 64; kk += 8) {
            uint32_t a0 = __float_as_uint(As[p][mrow0 + g][kk + tig]);
            uint32_t a1 = __float_as_uint(As[p][mrow0 + g + 8][kk + tig]);
            uint32_t a2 = __float_as_uint(As[p][mrow0 + g][kk + tig + 4]);
            uint32_t a3 = __float_as_uint(As[p][mrow0 + g + 8][kk + tig + 4]);
#pragma unroll
            for (int nt = 0; nt < 4; nt++) {
                uint32_t b0 = __float_as_uint(Bs[p][kk + tig][ncol0 + nt * 8 + g]);
                uint32_t b1v = __float_as_uint(Bs[p][kk + tig + 4][ncol0 + nt * 8 + g]);
                mma_tf32(acc[nt], a0, a1, a2, a3, b0, b1v);
            }
        }
    }

#pragma unroll
    for (int nt = 0; nt < 4; nt++) {
        int row = m0 + mrow0 + g;
        int col = n0 + ncol0 + nt * 8 + 2 * tig;
        float2 lo = make_float2(acc[nt].x, acc[nt].y);
        float2 hi = make_float2(acc[nt].z, acc[nt].w);
        if (z) {
            float b0v = b1[col], b1v = b1[col + 1];
            lo.x += b0v; lo.y += b1v;
            hi.x += b0v; hi.y += b1v;
        }
        *(float2*)&out[row * DD + col] = lo;
        *(float2*)&out[(row + 8) * DD + col] = hi;
    }
}

// ---------------------------------------------------------------------------
// prep_kernel (R11, unchanged): fused cross-GEMM + row stats + K consts.
// ---------------------------------------------------------------------------
#define CX_STRIDE 68
#define CX_BUF (32 * CX_STRIDE)
#define PREP_SMEM (3 * 2 * CX_BUF * 4)

__global__ __launch_bounds__(128) void prep_kernel(
    const float* __restrict__ gamma, const float* __restrict__ beta,
    const float* __restrict__ W2)
{
    const int t = threadIdx.x;
    const int lane = t & 31;
    const int w = t >> 5;

    if (blockIdx.x >= 392) {
        if (w == 0) {
            float k1 = 0.f, k2 = 0.f;
#pragma unroll
            for (int c = 0; c < 16; c++) {
                int d = lane + (c << 5);
                float wv = W2[d];
                k1 = fmaf(wv, gamma[d], k1);
                k2 = fmaf(wv, beta[d], k2);
            }
#pragma unroll
            for (int o = 16; o > 0; o >>= 1) {
                k1 += __shfl_xor_sync(0xffffffffu, k1, o);
                k2 += __shfl_xor_sync(0xffffffffu, k2, o);
            }
            if (lane == 0) { g_K[0] = k1; g_K[1] = k2; }
        }
        return;
    }

    if (blockIdx.x >= 136) {
        const int rid = (blockIdx.x - 136) * 4 + w;
        const float* row = g_LR + rid * DD;

        float s = 0.f, q = 0.f, a = 0.f;
#pragma unroll
        for (int c = 0; c < 4; c++) {
            int col = (lane + (c << 5)) << 2;
            float4 v = *(const float4*)&row[col];
            float4 gv = *(const float4*)&gamma[col];
            float4 wv = *(const float4*)&W2[col];
            s += v.x + v.y + v.z + v.w;
            q = fmaf(v.x, v.x, q); q = fmaf(v.y, v.y, q);
            q = fmaf(v.z, v.z, q); q = fmaf(v.w, v.w, q);
            a = fmaf(v.x, wv.x * gv.x, a); a = fmaf(v.y, wv.y * gv.y, a);
            a = fmaf(v.z, wv.z * gv.z, a); a = fmaf(v.w, wv.w * gv.w, a);
        }
#pragma unroll
        for (int o = 16; o > 0; o >>= 1) {
            s += __shfl_xor_sync(0xffffffffu, s, o);
            q += __shfl_xor_sync(0xffffffffu, q, o);
            a += __shfl_xor_sync(0xffffffffu, a, o);
        }
        if (lane == 0) { g_S[rid] = s; g_Q[rid] = q; g_A[rid] = a; }
        return;
    }

    float (*Ls)[32][CX_STRIDE] = (float(*)[32][CX_STRIDE])smem_dyn;
    float (*Rs)[32][CX_STRIDE] = (float(*)[32][CX_STRIDE])(smem_dyn + 3 * CX_BUF);

    int bid = blockIdx.x;
    int bi = 0, rem = bid;
    while (rem >= 16 - bi) { rem -= 16 - bi; bi++; }
    const int bj = bi + rem;

    const float* L = g_LR;
    const float* R = g_LR + NN * DD;
    const int m0 = bi * 32, n0 = bj * 32;
    const int g = lane >> 2, tig = lane & 3;
    const int mrow0 = (w >> 1) * 16, ncol0 = (w & 1) * 16;

    const int sr = t >> 4;
    const int sc = (t & 15) << 2;

    uint32_t l0addr[4], r0addr[4];
#pragma unroll
    for (int r = 0; r < 4; r++) {
        l0addr[r] = smem_u32(&Ls[0][sr + 8 * r][sc]);
        r0addr[r] = smem_u32(&Rs[0][sr + 8 * r][sc]);
    }

#define CX_ISSUE(p, k0)                                                       \
    {                                                                         \
        uint32_t off = (uint32_t)(p) * (CX_BUF * 4);                          \
        _Pragma("unroll")                                                     \
        for (int r = 0; r < 4; r++) {                                         \
            cp16(l0addr[r] + off, &L[(m0 + sr + 8 * r) * DD + (k0) + sc]);    \
            cp16(r0addr[r] + off, &R[(n0 + sr + 8 * r) * DD + (k0) + sc]);    \
        }                                                                     \
    }

    CX_ISSUE(0, 0);  CP_COMMIT();
    CX_ISSUE(1, 64); CP_COMMIT();

    float4 acc[2];
    acc[0] = make_float4(0.f, 0.f, 0.f, 0.f);
    acc[1] = make_float4(0.f, 0.f, 0.f, 0.f);

    for (int it = 0; it < 8; it++) {
        CP_WAIT1();
        __syncthreads();
        if (it < 6) {
            const int p = (it + 2) % 3;
            CX_ISSUE(p, (it + 2) * 64);
        }
        CP_COMMIT();

        const int p = it % 3;
#pragma unroll
        for (int kk = 0; kk < 64; kk += 8) {
            uint32_t a0 = __float_as_uint(Ls[p][mrow0 + g][kk + tig]);
            uint32_t a1 = __float_as_uint(Ls[p][mrow0 + g + 8][kk + tig]);
            uint32_t a2 = __float_as_uint(Ls[p][mrow0 + g][kk + tig + 4]);
            uint32_t a3 = __float_as_uint(Ls[p][mrow0 + g + 8][kk + tig + 4]);
#pragma unroll
            for (int nt = 0; nt < 2; nt++) {
                int nrow = ncol0 + nt * 8 + g;
                uint32_t b0 = __float_as_uint(Rs[p][nrow][kk + tig]);
                uint32_t b1v = __float_as_uint(Rs[p][nrow][kk + tig + 4]);
                mma_tf32(acc[nt], a0, a1, a2, a3, b0, b1v);
            }
        }
    }

#pragma unroll
    for (int nt = 0; nt < 2; nt++) {
        int row = m0 + mrow0 + g;
        int col = n0 + ncol0 + nt * 8 + 2 * tig;
        *(float2*)&g_C[row * NN + col] = make_float2(acc[nt].x, acc[nt].y);
        *(float2*)&g_C[(row + 8) * NN + col] = make_float2(acc[nt].z, acc[nt].w);
    }
}

// ---------------------------------------------------------------------------
// Pairwise kernel v6: R11 inner loop, jj split into 2 halves of 4 with a
// HARD non-unrolled half loop (branch between halves keeps live state 4-wide)
// -> ~60 regs -> 4 blocks/SM.
// ---------------------------------------------------------------------------
#define TI 8
#define TT (NN / TI)   // 64; blocks = 2080

__global__ __launch_bounds__(256, 4) void pair_kernel(
    const float* __restrict__ gamma, const float* __restrict__ beta,
    const float* __restrict__ W2, const float* __restrict__ b2,
    float* __restrict__ out)
{
    __shared__ float sl[TI][DD];
    __shared__ float sr_[TI][DD];
    __shared__ ull spg[8][32];
    __shared__ ull spb[8][32];
    __shared__ ull spw[8][32];
    __shared__ float sSl[TI], sQl[TI], sAl[TI];
    __shared__ float sSr[TI], sQr[TI], sBr[TI];
    __shared__ float sC[TI][TI];
    __shared__ float sK[2];

    int bid = blockIdx.x;
    int ti = (int)((2.0f * TT + 1.0f -
                    sqrtf((2.0f * TT + 1.0f) * (2.0f * TT + 1.0f) - 8.0f * (float)bid)) * 0.5f);
    if (ti < 0) ti = 0;
    if (ti > TT - 1) ti = TT - 1;
    while (ti > 0 && (ti * TT - ((ti * (ti - 1)) >> 1)) > bid) ti--;
    while (((ti + 1) * TT - (((ti + 1) * ti) >> 1)) <= bid) ti++;
    const int tj = ti + bid - (ti * TT - ((ti * (ti - 1)) >> 1));

    const int t = threadIdx.x;
    const int lane = t & 31;
    const int w = t >> 5;

    const float* L = g_LR;
    const float* R = g_LR + NN * DD;

#pragma unroll
    for (int c = 0; c < 4; c++) {
        int idx = c * 256 + t;
        int r = idx >> 7;
        int col = (idx & 127) << 2;
        *(float4*)&sl[r][col] = *(const float4*)&L[(ti * TI + r) * DD + col];
        *(float4*)&sr_[r][col] = *(const float4*)&R[(tj * TI + r) * DD + col];
    }
    {
        int k = t >> 5, ln = t & 31;
        int d = (k << 6) + (ln << 1);
        float2 gv = *(const float2*)&gamma[d];
        float2 bv = *(const float2*)&beta[d];
        float2 wv = *(const float2*)&W2[d];
        spg[k][ln] = pk(gv.x, gv.y);
        spb[k][ln] = pk(bv.x, bv.y);
        spw[k][ln] = pk(0.5f * wv.x, 0.5f * wv.y);
    }
    if (t < 8)              sSl[t] = g_S[ti * TI + t];
    else if (t < 16)        sQl[t - 8]  = g_Q[ti * TI + t - 8];
    else if (t < 24)        sAl[t - 16] = g_A[ti * TI + t - 16];
    else if (t < 32)        sSr[t - 24] = g_S[NN + tj * TI + t - 24];
    else if (t < 40)        sQr[t - 32] = g_Q[NN + tj * TI + t - 32];
    else if (t < 48)        sBr[t - 40] = g_A[NN + tj * TI + t - 40];
    else if (t < 112) {
        int li = t - 48;
        sC[li >> 3][li & 7] = g_C[(ti * TI + (li >> 3)) * NN + tj * TI + (li & 7)];
    }
    else if (t == 112)      sK[0] = g_K[0];
    else if (t == 113)      sK[1] = g_K[1];

    const ull C1 = pkdup(0.0356774081f);
    const ull C0 = pkdup(0.7978845608f);

    __syncthreads();

    const int i = ti * TI + w;
    const float b2v = b2[0];

    // Hard-bounded half loop: branch between halves keeps state 4-wide.
#pragma unroll 1
    for (int h = 0; h < 2; h++) {
        const int jb = h * 4;

        ull rstd2[4], accJ2[4];
        float ccs[4];
#pragma unroll
        for (int q = 0; q < 4; q++) {
            int jj = jb + q;
            float sum = sSl[w] + sSr[jj];
            float ssq = sQl[w] + sQr[jj] + 2.0f * sC[w][jj];
            float mu  = sum * (1.0f / DD);
            float var = fmaf(-mu, mu, ssq * (1.0f / DD));
            float rstd = rsqrtf(var + LN_EPS);
            float cc = -mu * rstd;
            float lin = 0.5f * fmaf(rstd, sAl[w] + sBr[jj], fmaf(cc, sK[0], sK[1]));
            rstd2[q] = pkdup(rstd);
            ccs[q] = cc;
            accJ2[q] = pkdup(lin * (1.0f / 64.0f));
        }

#pragma unroll
        for (int k = 0; k < 8; k++) {
            const int off = (k << 6) + (lane << 1);
            ull lk = *(const ull*)&sl[w][off];
            ull gk = spg[k][lane];
            ull bk = spb[k][lane];
            ull wk = spw[k][lane];
#pragma unroll
            for (int q = 0; q < 4; q++) {
                ull r2 = *(const ull*)&sr_[jb + q][off];
                ull v = add2(lk, r2);
                ull cc2 = pkdup(ccs[q]);
                ull x = fma2(v, rstd2[q], cc2);
                x = fma2(x, gk, bk);
                ull x2 = mul2(x, x);
                ull p = fma2(x2, C1, C0);
                ull u = mul2(x, p);
                float ulo, uhi;
                upk(u, ulo, uhi);
                ull th = pk(tanh_approx(ulo), tanh_approx(uhi));
                ull xw = mul2(x, wk);
                accJ2[q] = fma2(xw, th, accJ2[q]);
            }
        }

#pragma unroll
        for (int q = 0; q < 4; q++) {
            float lo, hi;
            upk(accJ2[q], lo, hi);
            float vsum = lo + hi;
#pragma unroll
            for (int o = 16; o > 0; o >>= 1)
                vsum += __shfl_xor_sync(0xffffffffu, vsum, o);
            int jj = jb + q;
            int j = tj * TI + jj;
            float zv = vsum + b2v;
            float sig = fmaf(0.5f, tanh_approx(0.5f * zv), 0.5f);
            if (lane == jj && i <= j) {
                out[i * NN + j] = sig;
                out[j * NN + i] = sig;
            }
        }
    }
}

// ---------------------------------------------------------------------------
extern "C" void kernel_launch(void* const* d_in, const int* in_sizes, int n_in,
                              void* d_out, int out_size)
{
    const float* E     = (const float*)d_in[0];
    const float* W1    = (const float*)d_in[1];
    const float* b1    = (const float*)d_in[2];
    const float* gamma = (const float*)d_in[3];
    const float* beta  = (const float*)d_in[4];
    const float* W2    = (const float*)d_in[5];
    const float* b2    = (const float*)d_in[6];
    float* out = (float*)d_out;

    cudaFuncSetAttribute(gemm_tc,
                         cudaFuncAttributeMaxDynamicSharedMemorySize, GEMM_SMEM);
    cudaFuncSetAttribute(prep_kernel,
                         cudaFuncAttributeMaxDynamicSharedMemorySize, PREP_SMEM);

    dim3 ggrid(NN / 64, NN / 64, 2);       // 128 blocks
    gemm_tc<<<ggrid, 256, GEMM_SMEM>>>(E, W1, b1);

    prep_kernel<<<393, 128, PREP_SMEM>>>(gamma, beta, W2);

    const int nblocks = TT * (TT + 1) / 2; // 2080
    pair_kernel<<<nblocks, 256>>>(gamma, beta, W2, b2, out);
}

// round 17
// speedup vs baseline: 1.6465x; 1.6465x over previous
#include <cuda_runtime.h>
#include <math.h>
#include <stdint.h>

#define NN 512
#define DD 512
#define LN_EPS 1e-5f

typedef unsigned long long ull;

// ---------------- f32x2 packed helpers ----------------
__device__ __forceinline__ ull pk(float lo, float hi) {
    ull r; asm("mov.b64 %0, {%1, %2};" : "=l"(r) : "f"(lo), "f"(hi)); return r;
}
__device__ __forceinline__ ull pkdup(float v) {
    ull r; asm("mov.b64 %0, {%1, %1};" : "=l"(r) : "f"(v)); return r;
}
__device__ __forceinline__ void upk(ull v, float& lo, float& hi) {
    asm("mov.b64 {%0, %1}, %2;" : "=f"(lo), "=f"(hi) : "l"(v));
}
__device__ __forceinline__ ull fma2(ull a, ull b, ull c) {
    ull r; asm("fma.rn.f32x2 %0, %1, %2, %3;" : "=l"(r) : "l"(a), "l"(b), "l"(c)); return r;
}
__device__ __forceinline__ ull add2(ull a, ull b) {
    ull r; asm("add.rn.f32x2 %0, %1, %2;" : "=l"(r) : "l"(a), "l"(b)); return r;
}
__device__ __forceinline__ ull mul2(ull a, ull b) {
    ull r; asm("mul.rn.f32x2 %0, %1, %2;" : "=l"(r) : "l"(a), "l"(b)); return r;
}
__device__ __forceinline__ float tanh_approx(float x) {
    float r; asm("tanh.approx.f32 %0, %1;" : "=f"(r) : "f"(x)); return r;
}
__device__ __forceinline__ void mma_tf32(float4& d,
    uint32_t a0, uint32_t a1, uint32_t a2, uint32_t a3,
    uint32_t b0, uint32_t b1)
{
    asm("mma.sync.aligned.m16n8k8.row.col.f32.tf32.tf32.f32 "
        "{%0,%1,%2,%3}, {%4,%5,%6,%7}, {%8,%9}, {%0,%1,%2,%3};"
        : "+f"(d.x), "+f"(d.y), "+f"(d.z), "+f"(d.w)
        : "r"(a0), "r"(a1), "r"(a2), "r"(a3), "r"(b0), "r"(b1));
}
__device__ __forceinline__ uint32_t smem_u32(const void* p) {
    uint32_t a;
    asm("{ .reg .u64 tmp; cvta.to.shared.u64 tmp, %1; cvt.u32.u64 %0, tmp; }"
        : "=r"(a) : "l"(p));
    return a;
}
__device__ __forceinline__ void cp16(uint32_t dst, const void* src) {
    asm volatile("cp.async.cg.shared.global [%0], [%1], 16;"
                 :: "r"(dst), "l"(src) : "memory");
}
#define CP_COMMIT() asm volatile("cp.async.commit_group;" ::: "memory")
#define CP_WAIT1()  asm volatile("cp.async.wait_group 1;" ::: "memory")

// Scratch (all L2-resident):
__device__ float g_LR[2 * NN * DD];   // left rows, then right rows (2 MB)
__device__ float g_C[NN * NN];        // cross dot L_i . R_j (upper tiles)
__device__ float g_S[2 * NN];         // row sums (L then R)
__device__ float g_Q[2 * NN];         // row sumsq
__device__ float g_A[2 * NN];         // dot(w*gamma, row)
__device__ float g_K[2];              // K1 = sum w*gamma, K2 = sum w*beta

extern __shared__ float smem_dyn[];

// ---------------------------------------------------------------------------
// Tensor-core GEMM (R11-measured, 11.3us): 64x64 tile, 256 threads (8 warps,
// warp tile 16x32), BK=64, 8 iterations, 3 full buffers, cp.async 2 ahead.
// ---------------------------------------------------------------------------
#define GA_STRIDE 68
#define GB_STRIDE 72
#define GA_BUF (64 * GA_STRIDE)
#define GB_BUF (64 * GB_STRIDE)
#define GEMM_SMEM (3 * (GA_BUF + GB_BUF) * 4)   // 107,520 B

__global__ __launch_bounds__(256) void gemm_tc(
    const float* __restrict__ E, const float* __restrict__ W1,
    const float* __restrict__ b1)
{
    float (*As)[64][GA_STRIDE] = (float(*)[64][GA_STRIDE])smem_dyn;
    float (*Bs)[64][GB_STRIDE] = (float(*)[64][GB_STRIDE])(smem_dyn + 3 * GA_BUF);

    const int z = blockIdx.z;
    const float* W = W1 + z * DD * DD;
    float* out = g_LR + z * NN * DD;

    const int m0 = blockIdx.y * 64;
    const int n0 = blockIdx.x * 64;
    const int t = threadIdx.x;
    const int lane = t & 31;
    const int w = t >> 5;
    const int g = lane >> 2, tig = lane & 3;
    const int mrow0 = (w >> 1) * 16;   // 0..48
    const int ncol0 = (w & 1) * 32;    // 0/32

    const int sr = t >> 4;             // 0..15
    const int sc = (t & 15) << 2;      // 0..60

    uint32_t a0addr[4], b0addr[4];
#pragma unroll
    for (int r = 0; r < 4; r++) {
        a0addr[r] = smem_u32(&As[0][sr + 16 * r][sc]);
        b0addr[r] = smem_u32(&Bs[0][sr + 16 * r][sc]);
    }

#define GEMM_ISSUE(p, k0)                                                     \
    {                                                                         \
        uint32_t ao = (uint32_t)(p) * (GA_BUF * 4);                           \
        uint32_t bo = (uint32_t)(p) * (GB_BUF * 4);                           \
        _Pragma("unroll")                                                     \
        for (int r = 0; r < 4; r++) {                                         \
            cp16(a0addr[r] + ao, &E[(m0 + sr + 16 * r) * DD + (k0) + sc]);    \
            cp16(b0addr[r] + bo, &W[((k0) + sr + 16 * r) * DD + n0 + sc]);    \
        }                                                                     \
    }

    GEMM_ISSUE(0, 0);  CP_COMMIT();
    GEMM_ISSUE(1, 64); CP_COMMIT();

    float4 acc[4];
#pragma unroll
    for (int nt = 0; nt < 4; nt++) acc[nt] = make_float4(0.f, 0.f, 0.f, 0.f);

    for (int it = 0; it < 8; it++) {
        CP_WAIT1();
        __syncthreads();
        if (it < 6) {
            const int p = (it + 2) % 3;
            GEMM_ISSUE(p, (it + 2) * 64);
        }
        CP_COMMIT();

        const int p = it % 3;
#pragma unroll
        for (int kk = 0; kk < 64; kk += 8) {
            uint32_t a0 = __float_as_uint(As[p][mrow0 + g][kk + tig]);
            uint32_t a1 = __float_as_uint(As[p][mrow0 + g + 8][kk + tig]);
            uint32_t a2 = __float_as_uint(As[p][mrow0 + g][kk + tig + 4]);
            uint32_t a3 = __float_as_uint(As[p][mrow0 + g + 8][kk + tig + 4]);
#pragma unroll
            for (int nt = 0; nt < 4; nt++) {
                uint32_t b0 = __float_as_uint(Bs[p][kk + tig][ncol0 + nt * 8 + g]);
                uint32_t b1v = __float_as_uint(Bs[p][kk + tig + 4][ncol0 + nt * 8 + g]);
                mma_tf32(acc[nt], a0, a1, a2, a3, b0, b1v);
            }
        }
    }

#pragma unroll
    for (int nt = 0; nt < 4; nt++) {
        int row = m0 + mrow0 + g;
        int col = n0 + ncol0 + nt * 8 + 2 * tig;
        float2 lo = make_float2(acc[nt].x, acc[nt].y);
        float2 hi = make_float2(acc[nt].z, acc[nt].w);
        if (z) {
            float b0v = b1[col], b1v = b1[col + 1];
            lo.x += b0v; lo.y += b1v;
            hi.x += b0v; hi.y += b1v;
        }
        *(float2*)&out[row * DD + col] = lo;
        *(float2*)&out[(row + 8) * DD + col] = hi;
    }
}

// ---------------------------------------------------------------------------
// prep_kernel (R11): fused cross-GEMM + row stats + K consts.
//   blocks [0,136): C = L @ R^T, 32x32 upper-tri tiles, BK=64, cp.async 3-buf.
//   blocks [136,392): row stats S/Q/A for 4 rows each.
//   block 392: K1 = sum w*gamma, K2 = sum w*beta.
// ---------------------------------------------------------------------------
#define CX_STRIDE 68
#define CX_BUF (32 * CX_STRIDE)
#define PREP_SMEM (3 * 2 * CX_BUF * 4)

__global__ __launch_bounds__(128) void prep_kernel(
    const float* __restrict__ gamma, const float* __restrict__ beta,
    const float* __restrict__ W2)
{
    const int t = threadIdx.x;
    const int lane = t & 31;
    const int w = t >> 5;

    if (blockIdx.x >= 392) {
        if (w == 0) {
            float k1 = 0.f, k2 = 0.f;
#pragma unroll
            for (int c = 0; c < 16; c++) {
                int d = lane + (c << 5);
                float wv = W2[d];
                k1 = fmaf(wv, gamma[d], k1);
                k2 = fmaf(wv, beta[d], k2);
            }
#pragma unroll
            for (int o = 16; o > 0; o >>= 1) {
                k1 += __shfl_xor_sync(0xffffffffu, k1, o);
                k2 += __shfl_xor_sync(0xffffffffu, k2, o);
            }
            if (lane == 0) { g_K[0] = k1; g_K[1] = k2; }
        }
        return;
    }

    if (blockIdx.x >= 136) {
        const int rid = (blockIdx.x - 136) * 4 + w;
        const float* row = g_LR + rid * DD;

        float s = 0.f, q = 0.f, a = 0.f;
#pragma unroll
        for (int c = 0; c < 4; c++) {
            int col = (lane + (c << 5)) << 2;
            float4 v = *(const float4*)&row[col];
            float4 gv = *(const float4*)&gamma[col];
            float4 wv = *(const float4*)&W2[col];
            s += v.x + v.y + v.z + v.w;
            q = fmaf(v.x, v.x, q); q = fmaf(v.y, v.y, q);
            q = fmaf(v.z, v.z, q); q = fmaf(v.w, v.w, q);
            a = fmaf(v.x, wv.x * gv.x, a); a = fmaf(v.y, wv.y * gv.y, a);
            a = fmaf(v.z, wv.z * gv.z, a); a = fmaf(v.w, wv.w * gv.w, a);
        }
#pragma unroll
        for (int o = 16; o > 0; o >>= 1) {
            s += __shfl_xor_sync(0xffffffffu, s, o);
            q += __shfl_xor_sync(0xffffffffu, q, o);
            a += __shfl_xor_sync(0xffffffffu, a, o);
        }
        if (lane == 0) { g_S[rid] = s; g_Q[rid] = q; g_A[rid] = a; }
        return;
    }

    float (*Ls)[32][CX_STRIDE] = (float(*)[32][CX_STRIDE])smem_dyn;
    float (*Rs)[32][CX_STRIDE] = (float(*)[32][CX_STRIDE])(smem_dyn + 3 * CX_BUF);

    int bid = blockIdx.x;
    int bi = 0, rem = bid;
    while (rem >= 16 - bi) { rem -= 16 - bi; bi++; }
    const int bj = bi + rem;

    const float* L = g_LR;
    const float* R = g_LR + NN * DD;
    const int m0 = bi * 32, n0 = bj * 32;
    const int g = lane >> 2, tig = lane & 3;
    const int mrow0 = (w >> 1) * 16, ncol0 = (w & 1) * 16;

    const int sr = t >> 4;
    const int sc = (t & 15) << 2;

    uint32_t l0addr[4], r0addr[4];
#pragma unroll
    for (int r = 0; r < 4; r++) {
        l0addr[r] = smem_u32(&Ls[0][sr + 8 * r][sc]);
        r0addr[r] = smem_u32(&Rs[0][sr + 8 * r][sc]);
    }

#define CX_ISSUE(p, k0)                                                       \
    {                                                                         \
        uint32_t off = (uint32_t)(p) * (CX_BUF * 4);                          \
        _Pragma("unroll")                                                     \
        for (int r = 0; r < 4; r++) {                                         \
            cp16(l0addr[r] + off, &L[(m0 + sr + 8 * r) * DD + (k0) + sc]);    \
            cp16(r0addr[r] + off, &R[(n0 + sr + 8 * r) * DD + (k0) + sc]);    \
        }                                                                     \
    }

    CX_ISSUE(0, 0);  CP_COMMIT();
    CX_ISSUE(1, 64); CP_COMMIT();

    float4 acc[2];
    acc[0] = make_float4(0.f, 0.f, 0.f, 0.f);
    acc[1] = make_float4(0.f, 0.f, 0.f, 0.f);

    for (int it = 0; it < 8; it++) {
        CP_WAIT1();
        __syncthreads();
        if (it < 6) {
            const int p = (it + 2) % 3;
            CX_ISSUE(p, (it + 2) * 64);
        }
        CP_COMMIT();

        const int p = it % 3;
#pragma unroll
        for (int kk = 0; kk < 64; kk += 8) {
            uint32_t a0 = __float_as_uint(Ls[p][mrow0 + g][kk + tig]);
            uint32_t a1 = __float_as_uint(Ls[p][mrow0 + g + 8][kk + tig]);
            uint32_t a2 = __float_as_uint(Ls[p][mrow0 + g][kk + tig + 4]);
            uint32_t a3 = __float_as_uint(Ls[p][mrow0 + g + 8][kk + tig + 4]);
#pragma unroll
            for (int nt = 0; nt < 2; nt++) {
                int nrow = ncol0 + nt * 8 + g;
                uint32_t b0 = __float_as_uint(Rs[p][nrow][kk + tig]);
                uint32_t b1v = __float_as_uint(Rs[p][nrow][kk + tig + 4]);
                mma_tf32(acc[nt], a0, a1, a2, a3, b0, b1v);
            }
        }
    }

#pragma unroll
    for (int nt = 0; nt < 2; nt++) {
        int row = m0 + mrow0 + g;
        int col = n0 + ncol0 + nt * 8 + 2 * tig;
        *(float2*)&g_C[row * NN + col] = make_float2(acc[nt].x, acc[nt].y);
        *(float2*)&g_C[(row + 8) * NN + col] = make_float2(acc[nt].z, acc[nt].w);
    }
}

// ---------------------------------------------------------------------------
// Pairwise kernel (R11-measured, 33.5us): single pass, stats via
// decomposition, params in smem, k outer / jj inner, 256 threads, 3 blocks/SM.
// ---------------------------------------------------------------------------
#define TI 8
#define TT (NN / TI)   // 64; blocks = 2080

__global__ __launch_bounds__(256, 3) void pair_kernel(
    const float* __restrict__ gamma, const float* __restrict__ beta,
    const float* __restrict__ W2, const float* __restrict__ b2,
    float* __restrict__ out)
{
    __shared__ float sl[TI][DD];
    __shared__ float sr_[TI][DD];
    __shared__ ull spg[8][32];
    __shared__ ull spb[8][32];
    __shared__ ull spw[8][32];
    __shared__ float sSl[TI], sQl[TI], sAl[TI];
    __shared__ float sSr[TI], sQr[TI], sBr[TI];
    __shared__ float sC[TI][TI];
    __shared__ float sK[2];

    int bid = blockIdx.x;
    int ti = (int)((2.0f * TT + 1.0f -
                    sqrtf((2.0f * TT + 1.0f) * (2.0f * TT + 1.0f) - 8.0f * (float)bid)) * 0.5f);
    if (ti < 0) ti = 0;
    if (ti > TT - 1) ti = TT - 1;
    while (ti > 0 && (ti * TT - ((ti * (ti - 1)) >> 1)) > bid) ti--;
    while (((ti + 1) * TT - (((ti + 1) * ti) >> 1)) <= bid) ti++;
    const int tj = ti + bid - (ti * TT - ((ti * (ti - 1)) >> 1));

    const int t = threadIdx.x;
    const int lane = t & 31;
    const int w = t >> 5;

    const float* L = g_LR;
    const float* R = g_LR + NN * DD;

#pragma unroll
    for (int c = 0; c < 4; c++) {
        int idx = c * 256 + t;
        int r = idx >> 7;
        int col = (idx & 127) << 2;
        *(float4*)&sl[r][col] = *(const float4*)&L[(ti * TI + r) * DD + col];
        *(float4*)&sr_[r][col] = *(const float4*)&R[(tj * TI + r) * DD + col];
    }
    {
        int k = t >> 5, ln = t & 31;
        int d = (k << 6) + (ln << 1);
        float2 gv = *(const float2*)&gamma[d];
        float2 bv = *(const float2*)&beta[d];
        float2 wv = *(const float2*)&W2[d];
        spg[k][ln] = pk(gv.x, gv.y);
        spb[k][ln] = pk(bv.x, bv.y);
        spw[k][ln] = pk(0.5f * wv.x, 0.5f * wv.y);
    }
    if (t < 8)              sSl[t] = g_S[ti * TI + t];
    else if (t < 16)        sQl[t - 8]  = g_Q[ti * TI + t - 8];
    else if (t < 24)        sAl[t - 16] = g_A[ti * TI + t - 16];
    else if (t < 32)        sSr[t - 24] = g_S[NN + tj * TI + t - 24];
    else if (t < 40)        sQr[t - 32] = g_Q[NN + tj * TI + t - 32];
    else if (t < 48)        sBr[t - 40] = g_A[NN + tj * TI + t - 40];
    else if (t < 112) {
        int li = t - 48;
        sC[li >> 3][li & 7] = g_C[(ti * TI + (li >> 3)) * NN + tj * TI + (li & 7)];
    }
    else if (t == 112)      sK[0] = g_K[0];
    else if (t == 113)      sK[1] = g_K[1];

    const ull C1 = pkdup(0.0356774081f);
    const ull C0 = pkdup(0.7978845608f);

    __syncthreads();

    const int i = ti * TI + w;
    const float Sl = sSl[w], Ql = sQl[w], Al = sAl[w];
    const float K1 = sK[0], K2 = sK[1];

    ull rstd2[TI], accJ2[TI];
    float ccs[TI];
#pragma unroll
    for (int jj = 0; jj < TI; jj++) {
        float sum = Sl + sSr[jj];
        float ssq = Ql + sQr[jj] + 2.0f * sC[w][jj];
        float mu  = sum * (1.0f / DD);
        float var = fmaf(-mu, mu, ssq * (1.0f / DD));
        float rstd = rsqrtf(var + LN_EPS);
        float cc = -mu * rstd;
        float lin = 0.5f * fmaf(rstd, Al + sBr[jj], fmaf(cc, K1, K2));
        rstd2[jj] = pkdup(rstd);
        ccs[jj] = cc;
        accJ2[jj] = pkdup(lin * (1.0f / 64.0f));
    }

#pragma unroll
    for (int k = 0; k < 8; k++) {
        const int off = (k << 6) + (lane << 1);
        ull lk = *(const ull*)&sl[w][off];
        ull gk = spg[k][lane];
        ull bk = spb[k][lane];
        ull wk = spw[k][lane];
#pragma unroll
        for (int jj = 0; jj < TI; jj++) {
            ull r2 = *(const ull*)&sr_[jj][off];
            ull v = add2(lk, r2);
            ull cc2 = pkdup(ccs[jj]);
            ull x = fma2(v, rstd2[jj], cc2);
            x = fma2(x, gk, bk);
            ull x2 = mul2(x, x);
            ull p = fma2(x2, C1, C0);
            ull u = mul2(x, p);
            float ulo, uhi;
            upk(u, ulo, uhi);
            ull th = pk(tanh_approx(ulo), tanh_approx(uhi));
            ull xw = mul2(x, wk);
            accJ2[jj] = fma2(xw, th, accJ2[jj]);
        }
    }

    const float b2v = b2[0];
#pragma unroll
    for (int jj = 0; jj < TI; jj++) {
        float lo, hi;
        upk(accJ2[jj], lo, hi);
        float vsum = lo + hi;
#pragma unroll
        for (int o = 16; o > 0; o >>= 1)
            vsum += __shfl_xor_sync(0xffffffffu, vsum, o);
        int j = tj * TI + jj;
        float zv = vsum + b2v;
        float sig = fmaf(0.5f, tanh_approx(0.5f * zv), 0.5f);
        if (lane == jj && i <= j) {
            out[i * NN + j] = sig;
            out[j * NN + i] = sig;
        }
    }
}

// ---------------------------------------------------------------------------
extern "C" void kernel_launch(void* const* d_in, const int* in_sizes, int n_in,
                              void* d_out, int out_size)
{
    const float* E     = (const float*)d_in[0];
    const float* W1    = (const float*)d_in[1];
    const float* b1    = (const float*)d_in[2];
    const float* gamma = (const float*)d_in[3];
    const float* beta  = (const float*)d_in[4];
    const float* W2    = (const float*)d_in[5];
    const float* b2    = (const float*)d_in[6];
    float* out = (float*)d_out;

    cudaFuncSetAttribute(gemm_tc,
                         cudaFuncAttributeMaxDynamicSharedMemorySize, GEMM_SMEM);
    cudaFuncSetAttribute(prep_kernel,
                         cudaFuncAttributeMaxDynamicSharedMemorySize, PREP_SMEM);

    dim3 ggrid(NN / 64, NN / 64, 2);       // 128 blocks
    gemm_tc<<<ggrid, 256, GEMM_SMEM>>>(E, W1, b1);

    prep_kernel<<<393, 128, PREP_SMEM>>>(gamma, beta, W2);

    const int nblocks = TT * (TT + 1) / 2; // 2080
    pair_kernel<<<nblocks, 256>>>(gamma, beta, W2, b2, out);
}